// round 1
// baseline (speedup 1.0000x reference)
#include <cuda_runtime.h>
#include <math.h>

// ---------------- problem constants ----------------
constexpr int kN    = 8192;
constexpr int kC0   = 64;
constexpr int kC1   = 32;
constexpr int kP0   = kC0*(kC0+1)/2;      // 2080
constexpr int kP1   = kC1*(kC1+1)/2;      // 528
constexpr int kA1   = kC1*(kC1-1)/2;      // 496
constexpr int kM0   = kC0 + kP0 + kP1;    // 2672
constexpr int kM1   = kC1 + kC0*kC1;      // 2080
constexpr int kG    = kM0 + kM1 + kA1 + kP1; // 5776
constexpr int kOUTW = 64 + 32*3 + 16*3 + 16*5; // 288

// ---------------- scratch (static device globals; no allocation) ----------------
__device__ float d_f0 [(size_t)kN*kM0];
__device__ float d_h  [(size_t)kN*kM0];
__device__ float d_g  [(size_t)kN*kG];
__device__ float d_f1 [3][(size_t)kN*kM1];
__device__ float d_f1e[3][(size_t)kN*kA1];
__device__ float d_f2 [5][(size_t)kN*kP1];

// ---------------- helpers ----------------
// decode p -> (a,b), a<=b+... for np.triu_indices(C, k)
__device__ __forceinline__ int2 triu_decode(int p, int C, int k)
{
    int Cm = C - k;                       // row a has Cm - a entries
    float t = 2.0f*Cm + 1.0f;
    int a = (int)((t - sqrtf(t*t - 8.0f*(float)p)) * 0.5f);
    if (a < 0) a = 0;
    if (a > Cm-1) a = Cm-1;
    // start(a) = a*Cm - a*(a-1)/2
    while (a > 0 && a*Cm - (a*(a-1))/2 > p) --a;
    while ((a+1)*Cm - ((a+1)*a)/2 <= p) ++a;
    int b = a + k + (p - (a*Cm - (a*(a-1))/2));
    return make_int2(a, b);
}

// ---------------- stage 1: feature construction ----------------
__global__ __launch_bounds__(256)
void build_features(const float* __restrict__ xs, const float* __restrict__ xv)
{
    const int n = blockIdx.x;
    __shared__ float s[kC0];
    __shared__ float v[kC1][3];
    const int t = threadIdx.x;
    if (t < kC0) s[t] = xs[(size_t)n*kC0 + t];
    if (t >= 128 && t < 128 + kC1*3) ((float*)v)[t-128] = xv[(size_t)n*kC1*3 + (t-128)];
    __syncthreads();

    const float RS2 = 0.70710678118654752f;  // 1/sqrt(2)
    const float RS3 = 0.57735026918962576f;  // 1/sqrt(3)
    const float S6  = 0.40824829046386302f;  // 1/sqrt(6)

    float* f0 = d_f0 + (size_t)n*kM0;
    // x_s passthrough
    if (t < kC0) f0[t] = s[t];
    // ss: upper-tri scalar products
    for (int p = t; p < kP0; p += 256) {
        int2 ab = triu_decode(p, kC0, 0);
        float c = (ab.x == ab.y) ? RS2 : 1.0f;
        f0[kC0 + p] = s[ab.x]*s[ab.y]*c;
    }
    // vv0: pair dot products
    for (int p = t; p < kP1; p += 256) {
        int2 ab = triu_decode(p, kC1, 0);
        float c = ((ab.x == ab.y) ? RS2 : 1.0f) * RS3;
        f0[kC0 + kP0 + p] =
            (v[ab.x][0]*v[ab.y][0] + v[ab.x][1]*v[ab.y][1] + v[ab.x][2]*v[ab.y][2]) * c;
    }
    // f1 planes (SoA over the 3 vector components): [x_v | s_c * v_w]
    for (int c = t; c < kM1; c += 256) {
        float e0, e1, e2;
        if (c < kC1) { e0 = v[c][0]; e1 = v[c][1]; e2 = v[c][2]; }
        else {
            int cc = (c - kC1) >> 5;
            int vv = (c - kC1) & 31;
            float sc = s[cc];
            e0 = sc*v[vv][0]; e1 = sc*v[vv][1]; e2 = sc*v[vv][2];
        }
        size_t idx = (size_t)n*kM1 + c;
        d_f1[0][idx] = e0; d_f1[1][idx] = e1; d_f1[2][idx] = e2;
    }
    // vv1e: cross products of strict pairs
    for (int p = t; p < kA1; p += 256) {
        int2 ab = triu_decode(p, kC1, 1);
        float ux = v[ab.x][0], uy = v[ab.x][1], uz = v[ab.x][2];
        float wx = v[ab.y][0], wy = v[ab.y][1], wz = v[ab.y][2];
        size_t idx = (size_t)n*kA1 + p;
        d_f1e[0][idx] = (uy*wz - uz*wy) * RS2;
        d_f1e[1][idx] = (uz*wx - ux*wz) * RS2;
        d_f1e[2][idx] = (ux*wy - uy*wx) * RS2;
    }
    // vv2: symmetric traceless l=2 products
    for (int p = t; p < kP1; p += 256) {
        int2 ab = triu_decode(p, kC1, 0);
        float c = (ab.x == ab.y) ? RS2 : 1.0f;
        float ax = v[ab.x][0], ay = v[ab.x][1], az = v[ab.x][2];
        float bx = v[ab.y][0], by = v[ab.y][1], bz = v[ab.y][2];
        size_t idx = (size_t)n*kP1 + p;
        d_f2[0][idx] = RS2*(ax*by + ay*bx)*c;
        d_f2[1][idx] = RS2*(ay*bz + az*by)*c;
        d_f2[2][idx] = RS2*(ax*bz + az*bx)*c;
        d_f2[3][idx] = RS2*(ax*bx - ay*by)*c;
        d_f2[4][idx] = S6*(-ax*bx - ay*by + 2.0f*az*bz)*c;
    }
}

// ---------------- stage 2/3: fp32 SGEMM 128x128x8, 8x8 microtile ----------------
template<bool SILU>
__global__ __launch_bounds__(256)
void sgemm_kernel(const float* __restrict__ A, const float* __restrict__ B,
                  float* __restrict__ C, int M, int K, int N)
{
    constexpr int BM = 128, BN = 128, BK = 8, TM = 8, TN = 8;
    __shared__ float As[BK][BM];
    __shared__ float Bs[BK][BN];
    const int tid = threadIdx.x;
    const int bx = blockIdx.x, by = blockIdx.y;

    const int rowA = tid >> 1;
    const int colA = (tid & 1) << 2;
    const int rowB = tid >> 5;
    const int colB = (tid & 31) << 2;
    const int tr = (tid >> 4) * TM;
    const int tc = (tid & 15) * TN;

    const float* Aptr = A + (size_t)(by*BM)*K;
    float acc[TM][TN];
    #pragma unroll
    for (int i = 0; i < TM; i++)
        #pragma unroll
        for (int j = 0; j < TN; j++) acc[i][j] = 0.0f;

    for (int k0 = 0; k0 < K; k0 += BK) {
        // A tile (M,K both tile-aligned for our shapes)
        float4 a4 = *reinterpret_cast<const float4*>(Aptr + (size_t)rowA*K + k0 + colA);
        As[colA+0][rowA] = a4.x; As[colA+1][rowA] = a4.y;
        As[colA+2][rowA] = a4.z; As[colA+3][rowA] = a4.w;
        // B tile with N guard (N % 4 == 0 for all shapes)
        int gcol = bx*BN + colB;
        float4 b4 = make_float4(0.f, 0.f, 0.f, 0.f);
        if (gcol < N)
            b4 = *reinterpret_cast<const float4*>(B + (size_t)(k0 + rowB)*N + gcol);
        *reinterpret_cast<float4*>(&Bs[rowB][colB]) = b4;
        __syncthreads();
        #pragma unroll
        for (int kk = 0; kk < BK; kk++) {
            float ar[TM], br[TN];
            float4 a0 = *reinterpret_cast<const float4*>(&As[kk][tr]);
            float4 a1 = *reinterpret_cast<const float4*>(&As[kk][tr+4]);
            ar[0]=a0.x; ar[1]=a0.y; ar[2]=a0.z; ar[3]=a0.w;
            ar[4]=a1.x; ar[5]=a1.y; ar[6]=a1.z; ar[7]=a1.w;
            float4 b0 = *reinterpret_cast<const float4*>(&Bs[kk][tc]);
            float4 b1 = *reinterpret_cast<const float4*>(&Bs[kk][tc+4]);
            br[0]=b0.x; br[1]=b0.y; br[2]=b0.z; br[3]=b0.w;
            br[4]=b1.x; br[5]=b1.y; br[6]=b1.z; br[7]=b1.w;
            #pragma unroll
            for (int i = 0; i < TM; i++)
                #pragma unroll
                for (int j = 0; j < TN; j++)
                    acc[i][j] = fmaf(ar[i], br[j], acc[i][j]);
        }
        __syncthreads();
    }
    #pragma unroll
    for (int i = 0; i < TM; i++) {
        int row = by*BM + tr + i;
        #pragma unroll
        for (int j = 0; j < TN; j++) {
            int col = bx*BN + tc + j;
            if (col < N) {
                float val = acc[i][j];
                if (SILU) val = val / (1.0f + __expf(-val));
                C[(size_t)row*N + col] = val;
            }
        }
    }
}

// ---------------- stage 4: apply gates in place ----------------
__global__ __launch_bounds__(256)
void gate_kernel()
{
    const int n = blockIdx.x;
    const int t = threadIdx.x;
    const float* g = d_g + (size_t)n*kG;
    float* f0 = d_f0 + (size_t)n*kM0;
    for (int c = t; c < kM0; c += 256) f0[c] *= g[c];
    for (int c = t; c < kM1; c += 256) {
        float gv = g[kM0 + c];
        size_t idx = (size_t)n*kM1 + c;
        d_f1[0][idx] *= gv; d_f1[1][idx] *= gv; d_f1[2][idx] *= gv;
    }
    for (int c = t; c < kA1; c += 256) {
        float gv = g[kM0 + kM1 + c];
        size_t idx = (size_t)n*kA1 + c;
        d_f1e[0][idx] *= gv; d_f1e[1][idx] *= gv; d_f1e[2][idx] *= gv;
    }
    for (int c = t; c < kP1; c += 256) {
        float gv = g[kM0 + kM1 + kA1 + c];
        size_t idx = (size_t)n*kP1 + c;
        #pragma unroll
        for (int m = 0; m < 5; m++) d_f2[m][idx] *= gv;
    }
}

// ---------------- stage 5: skinny output GEMMs with strided column placement ----------------
template<int OC>
__global__ __launch_bounds__(256)
void skinny_gemm(const float* __restrict__ A, const float* __restrict__ W,
                 float* __restrict__ out, int K, int outBase, int outStride)
{
    constexpr int BR = 32, BK = 32;
    constexpr int G   = 256 / OC;   // row groups per block
    constexpr int RPT = BR / G;     // rows per thread
    __shared__ float As[BR][BK + 1];
    __shared__ float Ws[BK][OC];
    const int tid  = threadIdx.x;
    const int row0 = blockIdx.x * BR;
    const int col  = tid % OC;
    const int rg   = tid / OC;

    float acc[RPT];
    #pragma unroll
    for (int r = 0; r < RPT; r++) acc[r] = 0.0f;

    for (int k0 = 0; k0 < K; k0 += BK) {
        int r  = tid >> 3;
        int kc = (tid & 7) << 2;
        float4 a4 = make_float4(0.f, 0.f, 0.f, 0.f);
        if (k0 + kc + 4 <= K)   // K % 4 == 0 for all our shapes
            a4 = *reinterpret_cast<const float4*>(A + (size_t)(row0 + r)*K + k0 + kc);
        As[r][kc] = a4.x; As[r][kc+1] = a4.y; As[r][kc+2] = a4.z; As[r][kc+3] = a4.w;
        for (int idx = tid; idx < BK*OC; idx += 256) {
            int kk = idx / OC, oo = idx % OC;
            Ws[kk][oo] = (k0 + kk < K) ? W[(size_t)(k0 + kk)*OC + oo] : 0.0f;
        }
        __syncthreads();
        #pragma unroll
        for (int kk = 0; kk < BK; kk++) {
            float wv = Ws[kk][col];
            #pragma unroll
            for (int rr = 0; rr < RPT; rr++)
                acc[rr] = fmaf(As[rg + rr*G][kk], wv, acc[rr]);
        }
        __syncthreads();
    }
    #pragma unroll
    for (int rr = 0; rr < RPT; rr++)
        out[(size_t)(row0 + rg + rr*G)*kOUTW + outBase + col*outStride] = acc[rr];
}

// ---------------- launch ----------------
extern "C" void kernel_launch(void* const* d_in, const int* in_sizes, int n_in,
                              void* d_out, int out_size)
{
    const float* xs  = (const float*)d_in[0];
    const float* xv  = (const float*)d_in[1];
    const float* w1  = (const float*)d_in[2];
    const float* w2  = (const float*)d_in[3];
    const float* w0  = (const float*)d_in[4];
    const float* w1o = (const float*)d_in[5];
    const float* w1e = (const float*)d_in[6];
    const float* w2e = (const float*)d_in[7];
    float* out = (float*)d_out;

    void *pf0, *ph, *pg, *pf1, *pf1e, *pf2;
    cudaGetSymbolAddress(&pf0,  d_f0);
    cudaGetSymbolAddress(&ph,   d_h);
    cudaGetSymbolAddress(&pg,   d_g);
    cudaGetSymbolAddress(&pf1,  d_f1);
    cudaGetSymbolAddress(&pf1e, d_f1e);
    cudaGetSymbolAddress(&pf2,  d_f2);
    float* f0v  = (float*)pf0;
    float* hv   = (float*)ph;
    float* gv   = (float*)pg;
    float* f1v  = (float*)pf1;
    float* f1ev = (float*)pf1e;
    float* f2v  = (float*)pf2;

    // stage 1: features
    build_features<<<kN, 256>>>(xs, xv);

    // stage 2: h = silu(f0 @ W1)   [8192 x 2672] @ [2672 x 2672]
    dim3 grid1((kM0 + 127) / 128, kN / 128);
    sgemm_kernel<true><<<grid1, 256>>>(f0v, w1, hv, kN, kM0, kM0);

    // stage 3: g = h @ W2          [8192 x 2672] @ [2672 x 5776]
    dim3 grid2((kG + 127) / 128, kN / 128);
    sgemm_kernel<false><<<grid2, 256>>>(hv, w2, gv, kN, kM0, kG);

    // stage 4: gates
    gate_kernel<<<kN, 256>>>();

    // stage 5: outputs into [N,288]
    skinny_gemm<64><<<kN/32, 256>>>(f0v, w0, out, kM0, 0, 1);
    for (int i = 0; i < 3; i++)
        skinny_gemm<32><<<kN/32, 256>>>(f1v + (size_t)i*kN*kM1, w1o, out, kM1, 64 + i, 3);
    for (int i = 0; i < 3; i++)
        skinny_gemm<16><<<kN/32, 256>>>(f1ev + (size_t)i*kN*kA1, w1e, out, kA1, 160 + i, 3);
    for (int m = 0; m < 5; m++)
        skinny_gemm<16><<<kN/32, 256>>>(f2v + (size_t)m*kN*kP1, w2e, out, kP1, 208 + m, 5);
}

// round 3
// speedup vs baseline: 2.5819x; 2.5819x over previous
#include <cuda_runtime.h>
#include <cuda_bf16.h>
#include <cstdint>
#include <math.h>

// ---------------- problem constants ----------------
constexpr int kN    = 8192;
constexpr int kC0   = 64;
constexpr int kC1   = 32;
constexpr int kP0   = kC0*(kC0+1)/2;      // 2080
constexpr int kP1   = kC1*(kC1+1)/2;      // 528
constexpr int kA1   = kC1*(kC1-1)/2;      // 496
constexpr int kM0   = kC0 + kP0 + kP1;    // 2672
constexpr int kM1   = kC1 + kC0*kC1;      // 2080
constexpr int kG    = kM0 + kM1 + kA1 + kP1; // 5776
constexpr int kOUTW = 64 + 32*3 + 16*3 + 16*5; // 288

// ---------------- scratch (static device globals; no allocation) ----------------
__device__ float d_f0 [(size_t)kN*kM0];
__device__ float d_g  [(size_t)kN*kG];
__device__ float d_f1 [3][(size_t)kN*kM1];
__device__ float d_f1e[3][(size_t)kN*kA1];
__device__ float d_f2 [5][(size_t)kN*kP1];
// bf16 hi/lo split operands for tensor-core GEMMs
__device__ __nv_bfloat16 d_f0hi[(size_t)kN*kM0];
__device__ __nv_bfloat16 d_f0lo[(size_t)kN*kM0];
__device__ __nv_bfloat16 d_hhi [(size_t)kN*kM0];
__device__ __nv_bfloat16 d_hlo [(size_t)kN*kM0];
__device__ __nv_bfloat16 d_w1thi[(size_t)kM0*kM0];   // [N=2672][K=2672] K-major
__device__ __nv_bfloat16 d_w1tlo[(size_t)kM0*kM0];
__device__ __nv_bfloat16 d_w2thi[(size_t)kG*kM0];    // [N=5776][K=2672] K-major
__device__ __nv_bfloat16 d_w2tlo[(size_t)kG*kM0];

// ---------------- PTX helpers (family-portable: sm_80+ mma.sync / cp.async) ----------------
__device__ __forceinline__ uint32_t smem_u32(const void* p) {
    uint32_t a;
    asm("{ .reg .u64 t; cvta.to.shared.u64 t, %1; cvt.u32.u64 %0, t; }" : "=r"(a) : "l"(p));
    return a;
}
__device__ __forceinline__ void cp16(uint32_t dst, const void* src, bool pred) {
    int sz = pred ? 16 : 0;
    asm volatile("cp.async.cg.shared.global [%0], [%1], 16, %2;"
                 :: "r"(dst), "l"(src), "r"(sz) : "memory");
}
__device__ __forceinline__ void cp_commit() {
    asm volatile("cp.async.commit_group;" ::: "memory");
}
template<int NG>
__device__ __forceinline__ void cp_wait() {
    asm volatile("cp.async.wait_group %0;" :: "n"(NG) : "memory");
}
__device__ __forceinline__ void ldm_x4(uint32_t* r, uint32_t addr) {
    asm volatile("ldmatrix.sync.aligned.m8n8.x4.shared.b16 {%0,%1,%2,%3}, [%4];"
                 : "=r"(r[0]), "=r"(r[1]), "=r"(r[2]), "=r"(r[3]) : "r"(addr));
}
__device__ __forceinline__ void ldm_x2(uint32_t* r, uint32_t addr) {
    asm volatile("ldmatrix.sync.aligned.m8n8.x2.shared.b16 {%0,%1}, [%2];"
                 : "=r"(r[0]), "=r"(r[1]) : "r"(addr));
}
__device__ __forceinline__ void mma_bf16(float* c, const uint32_t* a, const uint32_t* b) {
    asm volatile("mma.sync.aligned.m16n8k16.row.col.f32.bf16.bf16.f32 "
                 "{%0,%1,%2,%3}, {%4,%5,%6,%7}, {%8,%9}, {%0,%1,%2,%3};"
                 : "+f"(c[0]), "+f"(c[1]), "+f"(c[2]), "+f"(c[3])
                 : "r"(a[0]), "r"(a[1]), "r"(a[2]), "r"(a[3]), "r"(b[0]), "r"(b[1]));
}

// ---------------- triu decode ----------------
__device__ __forceinline__ int2 triu_decode(int p, int C, int k)
{
    int Cm = C - k;
    float t = 2.0f*Cm + 1.0f;
    int a = (int)((t - sqrtf(t*t - 8.0f*(float)p)) * 0.5f);
    if (a < 0) a = 0;
    if (a > Cm-1) a = Cm-1;
    while (a > 0 && a*Cm - (a*(a-1))/2 > p) --a;
    while ((a+1)*Cm - ((a+1)*a)/2 <= p) ++a;
    int b = a + k + (p - (a*Cm - (a*(a-1))/2));
    return make_int2(a, b);
}

__device__ __forceinline__ void split_store(float* f, __nv_bfloat16* fh, __nv_bfloat16* fl, int i, float x)
{
    f[i] = x;
    __nv_bfloat16 h = __float2bfloat16(x);
    fh[i] = h;
    fl[i] = __float2bfloat16(x - __bfloat162float(h));
}

// ---------------- stage 0: weight transpose + hi/lo split ----------------
__global__ __launch_bounds__(256)
void prep_weight(const float* __restrict__ W, __nv_bfloat16* __restrict__ Thi,
                 __nv_bfloat16* __restrict__ Tlo, int K, int N)
{
    __shared__ float tile[32][33];
    int kb = blockIdx.y*32, nb = blockIdx.x*32;
    int tx = threadIdx.x & 31, ty = threadIdx.x >> 5;   // 32 x 8
    for (int i = ty; i < 32; i += 8) {
        int k = kb + i, n = nb + tx;
        tile[i][tx] = (k < K && n < N) ? W[(size_t)k*N + n] : 0.f;
    }
    __syncthreads();
    for (int i = ty; i < 32; i += 8) {
        int n = nb + i, k = kb + tx;
        if (n < N && k < K) {
            float x = tile[tx][i];
            __nv_bfloat16 h = __float2bfloat16(x);
            Thi[(size_t)n*K + k] = h;
            Tlo[(size_t)n*K + k] = __float2bfloat16(x - __bfloat162float(h));
        }
    }
}

// ---------------- stage 1: feature construction ----------------
__global__ __launch_bounds__(256)
void build_features(const float* __restrict__ xs, const float* __restrict__ xv)
{
    const int n = blockIdx.x;
    __shared__ float s[kC0];
    __shared__ float v[kC1][3];
    const int t = threadIdx.x;
    if (t < kC0) s[t] = xs[(size_t)n*kC0 + t];
    if (t >= 128 && t < 128 + kC1*3) ((float*)v)[t-128] = xv[(size_t)n*kC1*3 + (t-128)];
    __syncthreads();

    const float RS2 = 0.70710678118654752f;
    const float RS3 = 0.57735026918962576f;
    const float S6  = 0.40824829046386302f;

    float* f0 = d_f0 + (size_t)n*kM0;
    __nv_bfloat16* fh = d_f0hi + (size_t)n*kM0;
    __nv_bfloat16* fl = d_f0lo + (size_t)n*kM0;

    if (t < kC0) split_store(f0, fh, fl, t, s[t]);
    for (int p = t; p < kP0; p += 256) {
        int2 ab = triu_decode(p, kC0, 0);
        float c = (ab.x == ab.y) ? RS2 : 1.0f;
        split_store(f0, fh, fl, kC0 + p, s[ab.x]*s[ab.y]*c);
    }
    for (int p = t; p < kP1; p += 256) {
        int2 ab = triu_decode(p, kC1, 0);
        float c = ((ab.x == ab.y) ? RS2 : 1.0f) * RS3;
        float d = (v[ab.x][0]*v[ab.y][0] + v[ab.x][1]*v[ab.y][1] + v[ab.x][2]*v[ab.y][2]) * c;
        split_store(f0, fh, fl, kC0 + kP0 + p, d);
    }
    for (int c = t; c < kM1; c += 256) {
        float e0, e1, e2;
        if (c < kC1) { e0 = v[c][0]; e1 = v[c][1]; e2 = v[c][2]; }
        else {
            int cc = (c - kC1) >> 5;
            int vv = (c - kC1) & 31;
            float sc = s[cc];
            e0 = sc*v[vv][0]; e1 = sc*v[vv][1]; e2 = sc*v[vv][2];
        }
        size_t idx = (size_t)n*kM1 + c;
        d_f1[0][idx] = e0; d_f1[1][idx] = e1; d_f1[2][idx] = e2;
    }
    for (int p = t; p < kA1; p += 256) {
        int2 ab = triu_decode(p, kC1, 1);
        float ux = v[ab.x][0], uy = v[ab.x][1], uz = v[ab.x][2];
        float wx = v[ab.y][0], wy = v[ab.y][1], wz = v[ab.y][2];
        size_t idx = (size_t)n*kA1 + p;
        d_f1e[0][idx] = (uy*wz - uz*wy) * RS2;
        d_f1e[1][idx] = (uz*wx - ux*wz) * RS2;
        d_f1e[2][idx] = (ux*wy - uy*wx) * RS2;
    }
    for (int p = t; p < kP1; p += 256) {
        int2 ab = triu_decode(p, kC1, 0);
        float c = (ab.x == ab.y) ? RS2 : 1.0f;
        float ax = v[ab.x][0], ay = v[ab.x][1], az = v[ab.x][2];
        float bx = v[ab.y][0], by = v[ab.y][1], bz = v[ab.y][2];
        size_t idx = (size_t)n*kP1 + p;
        d_f2[0][idx] = RS2*(ax*by + ay*bx)*c;
        d_f2[1][idx] = RS2*(ay*bz + az*by)*c;
        d_f2[2][idx] = RS2*(ax*bz + az*bx)*c;
        d_f2[3][idx] = RS2*(ax*bx - ay*by)*c;
        d_f2[4][idx] = S6*(-ax*bx - ay*by + 2.0f*az*bz)*c;
    }
}

// ---------------- bf16x3 HMMA GEMM: 128x128 tile, BK=32, cp.async double-buffer ----------------
constexpr int kTileStride = 80;                 // 64B data + 16B pad per row
constexpr int kTileBytes  = 128 * kTileStride;  // 10240
constexpr int kBufBytes   = 4 * kTileBytes;     // Ah, Al, Bh, Bl
constexpr int kGemmSmem   = 2 * kBufBytes;      // 81920

template<bool SILU>
__global__ __launch_bounds__(256, 1)
void mma_gemm(const __nv_bfloat16* __restrict__ Ahi, const __nv_bfloat16* __restrict__ Alo,
              const __nv_bfloat16* __restrict__ Bhi, const __nv_bfloat16* __restrict__ Blo,
              float* __restrict__ Cf, __nv_bfloat16* __restrict__ Chi, __nv_bfloat16* __restrict__ Clo,
              int K, int Nglob)
{
    extern __shared__ char smem[];
    const uint32_t sbase = smem_u32(smem);
    const int tid  = threadIdx.x;
    const int wid  = tid >> 5, lane = tid & 31;
    const int m0   = blockIdx.y * 128;
    const int n0   = blockIdx.x * 128;
    const int wm   = (wid & 1) * 64;      // warp M offset in tile
    const int wn   = (wid >> 1) * 32;     // warp N offset in tile

    float acc[4][4][4];
    #pragma unroll
    for (int i = 0; i < 4; i++)
        #pragma unroll
        for (int j = 0; j < 4; j++)
            #pragma unroll
            for (int q = 0; q < 4; q++) acc[i][j][q] = 0.0f;

    const int nChunks = (K + 31) / 32;    // 84

    // ---- loader: 2048 x 16B per chunk (Ah|Al|Bh|Bl, 128 rows x 64B each) ----
    auto load_chunk = [&](int c) {
        const uint32_t db = sbase + (c & 1) * kBufBytes;
        const int k0 = c * 32;
        #pragma unroll
        for (int t = 0; t < 8; t++) {
            int idx  = t * 256 + tid;           // 0..2047
            int tile = idx >> 9;                // 512 chunks per tile
            int rem  = idx & 511;
            int row  = rem >> 2;
            int kc   = rem & 3;
            int gk   = k0 + kc * 8;
            bool kok = gk < K;
            uint32_t dst = db + tile * kTileBytes + row * kTileStride + kc * 16;
            const __nv_bfloat16* src;
            bool ok;
            if (tile < 2) {
                const __nv_bfloat16* base = (tile == 0) ? Ahi : Alo;
                src = base + (size_t)(m0 + row) * K + (kok ? gk : 0);
                ok  = kok;
            } else {
                const __nv_bfloat16* base = (tile == 2) ? Bhi : Blo;
                int gn = n0 + row;
                bool nok = gn < Nglob;
                src = base + (size_t)(nok ? gn : 0) * K + (kok ? gk : 0);
                ok  = kok && nok;
            }
            cp16(dst, src, ok);
        }
        cp_commit();
    };

    load_chunk(0);

    for (int c = 0; c < nChunks; c++) {
        if (c + 1 < nChunks) { load_chunk(c + 1); cp_wait<1>(); }
        else                 { cp_wait<0>(); }
        __syncthreads();

        const uint32_t db = sbase + (c & 1) * kBufBytes;
        const uint32_t aH = db, aL = db + kTileBytes;
        const uint32_t bH = db + 2*kTileBytes, bL = db + 3*kTileBytes;

        #pragma unroll
        for (int ks = 0; ks < 2; ks++) {
            uint32_t ah[4][4], al[4][4], bh[4][2], bl[4][2];
            const int arow = wm + (lane & 15);
            const int acol = ks * 32 + (lane >> 4) * 16;   // bytes
            #pragma unroll
            for (int mt = 0; mt < 4; mt++) {
                uint32_t off = (uint32_t)(arow + mt*16) * kTileStride + acol;
                ldm_x4(ah[mt], aH + off);
                ldm_x4(al[mt], aL + off);
            }
            const int li = lane & 15;
            const int brow = wn + (li & 7);
            const int bcol = ks * 32 + (li >> 3) * 16;     // bytes
            #pragma unroll
            for (int nt = 0; nt < 4; nt++) {
                uint32_t off = (uint32_t)(brow + nt*8) * kTileStride + bcol;
                ldm_x2(bh[nt], bH + off);
                ldm_x2(bl[nt], bL + off);
            }
            #pragma unroll
            for (int mt = 0; mt < 4; mt++)
                #pragma unroll
                for (int nt = 0; nt < 4; nt++) {
                    mma_bf16(acc[mt][nt], ah[mt], bh[nt]);
                    mma_bf16(acc[mt][nt], ah[mt], bl[nt]);
                    mma_bf16(acc[mt][nt], al[mt], bh[nt]);
                }
        }
        __syncthreads();
    }

    // ---- epilogue ----
    #pragma unroll
    for (int mt = 0; mt < 4; mt++) {
        #pragma unroll
        for (int nt = 0; nt < 4; nt++) {
            int row = m0 + wm + mt*16 + (lane >> 2);
            int col = n0 + wn + nt*8 + (lane & 3) * 2;
            #pragma unroll
            for (int half = 0; half < 2; half++) {
                int r = row + half * 8;
                float v0 = acc[mt][nt][half*2 + 0];
                float v1 = acc[mt][nt][half*2 + 1];
                if (col < Nglob) {
                    if (SILU) {
                        v0 = v0 / (1.0f + __expf(-v0));
                        v1 = v1 / (1.0f + __expf(-v1));
                        __nv_bfloat16 h0 = __float2bfloat16(v0);
                        __nv_bfloat16 h1 = __float2bfloat16(v1);
                        size_t o = (size_t)r * Nglob + col;
                        Chi[o]   = h0;
                        Chi[o+1] = h1;
                        Clo[o]   = __float2bfloat16(v0 - __bfloat162float(h0));
                        Clo[o+1] = __float2bfloat16(v1 - __bfloat162float(h1));
                    } else {
                        size_t o = (size_t)r * Nglob + col;
                        Cf[o]   = v0;
                        Cf[o+1] = v1;
                    }
                }
            }
        }
    }
}

// ---------------- stage 4: apply gates in place ----------------
__global__ __launch_bounds__(256)
void gate_kernel()
{
    const int n = blockIdx.x;
    const int t = threadIdx.x;
    const float* g = d_g + (size_t)n*kG;
    float* f0 = d_f0 + (size_t)n*kM0;
    for (int c = t; c < kM0; c += 256) f0[c] *= g[c];
    for (int c = t; c < kM1; c += 256) {
        float gv = g[kM0 + c];
        size_t idx = (size_t)n*kM1 + c;
        d_f1[0][idx] *= gv; d_f1[1][idx] *= gv; d_f1[2][idx] *= gv;
    }
    for (int c = t; c < kA1; c += 256) {
        float gv = g[kM0 + kM1 + c];
        size_t idx = (size_t)n*kA1 + c;
        d_f1e[0][idx] *= gv; d_f1e[1][idx] *= gv; d_f1e[2][idx] *= gv;
    }
    for (int c = t; c < kP1; c += 256) {
        float gv = g[kM0 + kM1 + kA1 + c];
        size_t idx = (size_t)n*kP1 + c;
        #pragma unroll
        for (int m = 0; m < 5; m++) d_f2[m][idx] *= gv;
    }
}

// ---------------- stage 5: skinny output GEMMs ----------------
template<int OC>
__global__ __launch_bounds__(256)
void skinny_gemm(const float* __restrict__ A, const float* __restrict__ W,
                 float* __restrict__ out, int K, int outBase, int outStride)
{
    constexpr int BR = 32, BK = 32;
    constexpr int G   = 256 / OC;
    constexpr int RPT = BR / G;
    __shared__ float As[BR][BK + 1];
    __shared__ float Ws[BK][OC];
    const int tid  = threadIdx.x;
    const int row0 = blockIdx.x * BR;
    const int col  = tid % OC;
    const int rg   = tid / OC;

    float acc[RPT];
    #pragma unroll
    for (int r = 0; r < RPT; r++) acc[r] = 0.0f;

    for (int k0 = 0; k0 < K; k0 += BK) {
        int r  = tid >> 3;
        int kc = (tid & 7) << 2;
        float4 a4 = make_float4(0.f, 0.f, 0.f, 0.f);
        if (k0 + kc + 4 <= K)
            a4 = *reinterpret_cast<const float4*>(A + (size_t)(row0 + r)*K + k0 + kc);
        As[r][kc] = a4.x; As[r][kc+1] = a4.y; As[r][kc+2] = a4.z; As[r][kc+3] = a4.w;
        for (int idx = tid; idx < BK*OC; idx += 256) {
            int kk = idx / OC, oo = idx % OC;
            Ws[kk][oo] = (k0 + kk < K) ? W[(size_t)(k0 + kk)*OC + oo] : 0.0f;
        }
        __syncthreads();
        #pragma unroll
        for (int kk = 0; kk < BK; kk++) {
            float wv = Ws[kk][col];
            #pragma unroll
            for (int rr = 0; rr < RPT; rr++)
                acc[rr] = fmaf(As[rg + rr*G][kk], wv, acc[rr]);
        }
        __syncthreads();
    }
    #pragma unroll
    for (int rr = 0; rr < RPT; rr++)
        out[(size_t)(row0 + rg + rr*G)*kOUTW + outBase + col*outStride] = acc[rr];
}

// ---------------- launch ----------------
extern "C" void kernel_launch(void* const* d_in, const int* in_sizes, int n_in,
                              void* d_out, int out_size)
{
    const float* xs  = (const float*)d_in[0];
    const float* xv  = (const float*)d_in[1];
    const float* w1  = (const float*)d_in[2];
    const float* w2  = (const float*)d_in[3];
    const float* w0  = (const float*)d_in[4];
    const float* w1o = (const float*)d_in[5];
    const float* w1e = (const float*)d_in[6];
    const float* w2e = (const float*)d_in[7];
    float* out = (float*)d_out;

    void *pf0, *pg, *pf1, *pf1e, *pf2;
    void *pf0hi, *pf0lo, *phhi, *phlo, *pw1h, *pw1l, *pw2h, *pw2l;
    cudaGetSymbolAddress(&pf0,  d_f0);
    cudaGetSymbolAddress(&pg,   d_g);
    cudaGetSymbolAddress(&pf1,  d_f1);
    cudaGetSymbolAddress(&pf1e, d_f1e);
    cudaGetSymbolAddress(&pf2,  d_f2);
    cudaGetSymbolAddress(&pf0hi, d_f0hi);
    cudaGetSymbolAddress(&pf0lo, d_f0lo);
    cudaGetSymbolAddress(&phhi,  d_hhi);
    cudaGetSymbolAddress(&phlo,  d_hlo);
    cudaGetSymbolAddress(&pw1h,  d_w1thi);
    cudaGetSymbolAddress(&pw1l,  d_w1tlo);
    cudaGetSymbolAddress(&pw2h,  d_w2thi);
    cudaGetSymbolAddress(&pw2l,  d_w2tlo);

    float* f0v  = (float*)pf0;
    float* gv   = (float*)pg;
    float* f1v  = (float*)pf1;
    float* f1ev = (float*)pf1e;
    float* f2v  = (float*)pf2;
    __nv_bfloat16* f0hi = (__nv_bfloat16*)pf0hi;
    __nv_bfloat16* f0lo = (__nv_bfloat16*)pf0lo;
    __nv_bfloat16* hhi  = (__nv_bfloat16*)phhi;
    __nv_bfloat16* hlo  = (__nv_bfloat16*)phlo;
    __nv_bfloat16* w1th = (__nv_bfloat16*)pw1h;
    __nv_bfloat16* w1tl = (__nv_bfloat16*)pw1l;
    __nv_bfloat16* w2th = (__nv_bfloat16*)pw2h;
    __nv_bfloat16* w2tl = (__nv_bfloat16*)pw2l;

    cudaFuncSetAttribute(mma_gemm<true>,  cudaFuncAttributeMaxDynamicSharedMemorySize, kGemmSmem);
    cudaFuncSetAttribute(mma_gemm<false>, cudaFuncAttributeMaxDynamicSharedMemorySize, kGemmSmem);

    // stage 0: weight transpose + split
    prep_weight<<<dim3((kM0+31)/32, (kM0+31)/32), 256>>>(w1, w1th, w1tl, kM0, kM0);
    prep_weight<<<dim3((kG +31)/32, (kM0+31)/32), 256>>>(w2, w2th, w2tl, kM0, kG);

    // stage 1: features (+ f0 hi/lo split)
    build_features<<<kN, 256>>>(xs, xv);

    // stage 2: h = silu(f0 @ W1) -> hhi/hlo   [8192 x 2672]
    {
        dim3 grid((kM0 + 127)/128, kN/128);
        mma_gemm<true><<<grid, 256, kGemmSmem>>>(f0hi, f0lo, w1th, w1tl,
                                                 nullptr, hhi, hlo, kM0, kM0);
    }
    // stage 3: g = h @ W2 (fp32)              [8192 x 5776]
    {
        dim3 grid((kG + 127)/128, kN/128);
        mma_gemm<false><<<grid, 256, kGemmSmem>>>(hhi, hlo, w2th, w2tl,
                                                  gv, nullptr, nullptr, kM0, kG);
    }

    // stage 4: gates
    gate_kernel<<<kN, 256>>>();

    // stage 5: outputs into [N,288]
    skinny_gemm<64><<<kN/32, 256>>>(f0v, w0, out, kM0, 0, 1);
    for (int i = 0; i < 3; i++)
        skinny_gemm<32><<<kN/32, 256>>>(f1v + (size_t)i*kN*kM1, w1o, out, kM1, 64 + i, 3);
    for (int i = 0; i < 3; i++)
        skinny_gemm<16><<<kN/32, 256>>>(f1ev + (size_t)i*kN*kA1, w1e, out, kA1, 160 + i, 3);
    for (int m = 0; m < 5; m++)
        skinny_gemm<16><<<kN/32, 256>>>(f2v + (size_t)m*kN*kP1, w2e, out, kP1, 208 + m, 5);
}

// round 4
// speedup vs baseline: 2.7461x; 1.0636x over previous
#include <cuda_runtime.h>
#include <cuda_bf16.h>
#include <cstdint>
#include <math.h>

// ---------------- problem constants ----------------
constexpr int kN    = 8192;
constexpr int kC0   = 64;
constexpr int kC1   = 32;
constexpr int kP0   = kC0*(kC0+1)/2;      // 2080
constexpr int kP1   = kC1*(kC1+1)/2;      // 528
constexpr int kA1   = kC1*(kC1-1)/2;      // 496
constexpr int kM0   = kC0 + kP0 + kP1;    // 2672
constexpr int kM1   = kC1 + kC0*kC1;      // 2080
constexpr int kG    = kM0 + kM1 + kA1 + kP1; // 5776
constexpr int kOUTW = 64 + 32*3 + 16*3 + 16*5; // 288

// ---------------- scratch (static device globals; no allocation) ----------------
__device__ float d_f0 [(size_t)kN*kM0];
__device__ float d_g  [(size_t)kN*kG];
__device__ float d_f1 [3][(size_t)kN*kM1];
__device__ float d_f1e[3][(size_t)kN*kA1];
__device__ float d_f2 [5][(size_t)kN*kP1];
__device__ __nv_bfloat16 d_f0hi[(size_t)kN*kM0];
__device__ __nv_bfloat16 d_f0lo[(size_t)kN*kM0];
__device__ __nv_bfloat16 d_hhi [(size_t)kN*kM0];
__device__ __nv_bfloat16 d_hlo [(size_t)kN*kM0];
__device__ __nv_bfloat16 d_w1thi[(size_t)kM0*kM0];   // [N=2672][K=2672] K-major
__device__ __nv_bfloat16 d_w1tlo[(size_t)kM0*kM0];
__device__ __nv_bfloat16 d_w2thi[(size_t)kG*kM0];    // [N=5776][K=2672] K-major
__device__ __nv_bfloat16 d_w2tlo[(size_t)kG*kM0];

// ---------------- PTX helpers (family-portable: sm_80+ mma.sync / cp.async) ----------------
__device__ __forceinline__ uint32_t smem_u32(const void* p) {
    uint32_t a;
    asm("{ .reg .u64 t; cvta.to.shared.u64 t, %1; cvt.u32.u64 %0, t; }" : "=r"(a) : "l"(p));
    return a;
}
__device__ __forceinline__ void cp16(uint32_t dst, const void* src, bool pred) {
    int sz = pred ? 16 : 0;
    asm volatile("cp.async.cg.shared.global [%0], [%1], 16, %2;"
                 :: "r"(dst), "l"(src), "r"(sz) : "memory");
}
__device__ __forceinline__ void cp_commit() {
    asm volatile("cp.async.commit_group;" ::: "memory");
}
template<int NG>
__device__ __forceinline__ void cp_wait() {
    asm volatile("cp.async.wait_group %0;" :: "n"(NG) : "memory");
}
__device__ __forceinline__ void ldm_x4(uint32_t* r, uint32_t addr) {
    asm volatile("ldmatrix.sync.aligned.m8n8.x4.shared.b16 {%0,%1,%2,%3}, [%4];"
                 : "=r"(r[0]), "=r"(r[1]), "=r"(r[2]), "=r"(r[3]) : "r"(addr));
}
__device__ __forceinline__ void ldm_x2(uint32_t* r, uint32_t addr) {
    asm volatile("ldmatrix.sync.aligned.m8n8.x2.shared.b16 {%0,%1}, [%2];"
                 : "=r"(r[0]), "=r"(r[1]) : "r"(addr));
}
__device__ __forceinline__ void mma_bf16(float* c, const uint32_t* a, const uint32_t* b) {
    asm volatile("mma.sync.aligned.m16n8k16.row.col.f32.bf16.bf16.f32 "
                 "{%0,%1,%2,%3}, {%4,%5,%6,%7}, {%8,%9}, {%0,%1,%2,%3};"
                 : "+f"(c[0]), "+f"(c[1]), "+f"(c[2]), "+f"(c[3])
                 : "r"(a[0]), "r"(a[1]), "r"(a[2]), "r"(a[3]), "r"(b[0]), "r"(b[1]));
}

// ---------------- triu decode ----------------
__device__ __forceinline__ int2 triu_decode(int p, int C, int k)
{
    int Cm = C - k;
    float t = 2.0f*Cm + 1.0f;
    int a = (int)((t - sqrtf(t*t - 8.0f*(float)p)) * 0.5f);
    if (a < 0) a = 0;
    if (a > Cm-1) a = Cm-1;
    while (a > 0 && a*Cm - (a*(a-1))/2 > p) --a;
    while ((a+1)*Cm - ((a+1)*a)/2 <= p) ++a;
    int b = a + k + (p - (a*Cm - (a*(a-1))/2));
    return make_int2(a, b);
}

__device__ __forceinline__ void split_store(float* f, __nv_bfloat16* fh, __nv_bfloat16* fl, int i, float x)
{
    f[i] = x;
    __nv_bfloat16 h = __float2bfloat16(x);
    fh[i] = h;
    fl[i] = __float2bfloat16(x - __bfloat162float(h));
}

// ---------------- stage 0: weight transpose + hi/lo split ----------------
__global__ __launch_bounds__(256)
void prep_weight(const float* __restrict__ W, __nv_bfloat16* __restrict__ Thi,
                 __nv_bfloat16* __restrict__ Tlo, int K, int N)
{
    __shared__ float tile[32][33];
    int kb = blockIdx.y*32, nb = blockIdx.x*32;
    int tx = threadIdx.x & 31, ty = threadIdx.x >> 5;   // 32 x 8
    for (int i = ty; i < 32; i += 8) {
        int k = kb + i, n = nb + tx;
        tile[i][tx] = (k < K && n < N) ? W[(size_t)k*N + n] : 0.f;
    }
    __syncthreads();
    for (int i = ty; i < 32; i += 8) {
        int n = nb + i, k = kb + tx;
        if (n < N && k < K) {
            float x = tile[tx][i];
            __nv_bfloat16 h = __float2bfloat16(x);
            Thi[(size_t)n*K + k] = h;
            Tlo[(size_t)n*K + k] = __float2bfloat16(x - __bfloat162float(h));
        }
    }
}

// ---------------- stage 1: feature construction ----------------
__global__ __launch_bounds__(256)
void build_features(const float* __restrict__ xs, const float* __restrict__ xv)
{
    const int n = blockIdx.x;
    __shared__ float s[kC0];
    __shared__ float v[kC1][3];
    const int t = threadIdx.x;
    if (t < kC0) s[t] = xs[(size_t)n*kC0 + t];
    if (t >= 128 && t < 128 + kC1*3) ((float*)v)[t-128] = xv[(size_t)n*kC1*3 + (t-128)];
    __syncthreads();

    const float RS2 = 0.70710678118654752f;
    const float RS3 = 0.57735026918962576f;
    const float S6  = 0.40824829046386302f;

    float* f0 = d_f0 + (size_t)n*kM0;
    __nv_bfloat16* fh = d_f0hi + (size_t)n*kM0;
    __nv_bfloat16* fl = d_f0lo + (size_t)n*kM0;

    if (t < kC0) split_store(f0, fh, fl, t, s[t]);
    for (int p = t; p < kP0; p += 256) {
        int2 ab = triu_decode(p, kC0, 0);
        float c = (ab.x == ab.y) ? RS2 : 1.0f;
        split_store(f0, fh, fl, kC0 + p, s[ab.x]*s[ab.y]*c);
    }
    for (int p = t; p < kP1; p += 256) {
        int2 ab = triu_decode(p, kC1, 0);
        float c = ((ab.x == ab.y) ? RS2 : 1.0f) * RS3;
        float d = (v[ab.x][0]*v[ab.y][0] + v[ab.x][1]*v[ab.y][1] + v[ab.x][2]*v[ab.y][2]) * c;
        split_store(f0, fh, fl, kC0 + kP0 + p, d);
    }
    for (int c = t; c < kM1; c += 256) {
        float e0, e1, e2;
        if (c < kC1) { e0 = v[c][0]; e1 = v[c][1]; e2 = v[c][2]; }
        else {
            int cc = (c - kC1) >> 5;
            int vv = (c - kC1) & 31;
            float sc = s[cc];
            e0 = sc*v[vv][0]; e1 = sc*v[vv][1]; e2 = sc*v[vv][2];
        }
        size_t idx = (size_t)n*kM1 + c;
        d_f1[0][idx] = e0; d_f1[1][idx] = e1; d_f1[2][idx] = e2;
    }
    for (int p = t; p < kA1; p += 256) {
        int2 ab = triu_decode(p, kC1, 1);
        float ux = v[ab.x][0], uy = v[ab.x][1], uz = v[ab.x][2];
        float wx = v[ab.y][0], wy = v[ab.y][1], wz = v[ab.y][2];
        size_t idx = (size_t)n*kA1 + p;
        d_f1e[0][idx] = (uy*wz - uz*wy) * RS2;
        d_f1e[1][idx] = (uz*wx - ux*wz) * RS2;
        d_f1e[2][idx] = (ux*wy - uy*wx) * RS2;
    }
    for (int p = t; p < kP1; p += 256) {
        int2 ab = triu_decode(p, kC1, 0);
        float c = (ab.x == ab.y) ? RS2 : 1.0f;
        float ax = v[ab.x][0], ay = v[ab.x][1], az = v[ab.x][2];
        float bx = v[ab.y][0], by = v[ab.y][1], bz = v[ab.y][2];
        size_t idx = (size_t)n*kP1 + p;
        d_f2[0][idx] = RS2*(ax*by + ay*bx)*c;
        d_f2[1][idx] = RS2*(ay*bz + az*by)*c;
        d_f2[2][idx] = RS2*(ax*bz + az*bx)*c;
        d_f2[3][idx] = RS2*(ax*bx - ay*by)*c;
        d_f2[4][idx] = S6*(-ax*bx - ay*by + 2.0f*az*bz)*c;
    }
}

// ---------------- bf16x3 HMMA GEMM: 128x256 tile, 512 thr, BK=32, double-buffered ----------------
constexpr int kRowStride  = 80;                     // 64B data + 16B pad
constexpr int kATileBytes = 128 * kRowStride;       // 10240
constexpr int kBTileBytes = 256 * kRowStride;       // 20480
constexpr int kBufBytes   = 2*kATileBytes + 2*kBTileBytes; // 61440
constexpr int kGemmSmem   = 2 * kBufBytes;          // 122880

template<bool SILU>
__global__ __launch_bounds__(512, 1)
void mma_gemm(const __nv_bfloat16* __restrict__ Ahi, const __nv_bfloat16* __restrict__ Alo,
              const __nv_bfloat16* __restrict__ Bhi, const __nv_bfloat16* __restrict__ Blo,
              float* __restrict__ Cf, __nv_bfloat16* __restrict__ Chi, __nv_bfloat16* __restrict__ Clo,
              int K, int Nglob)
{
    extern __shared__ char smem[];
    const uint32_t sbase = smem_u32(smem);
    const int tid  = threadIdx.x;
    const int wid  = tid >> 5, lane = tid & 31;
    const int m0   = blockIdx.y * 128;
    const int n0   = blockIdx.x * 256;
    const int wm   = (wid & 1) * 64;      // 2 M-warps
    const int wn   = (wid >> 1) * 32;     // 8 N-warps

    float acc[4][4][4];
    #pragma unroll
    for (int i = 0; i < 4; i++)
        #pragma unroll
        for (int j = 0; j < 4; j++)
            #pragma unroll
            for (int q = 0; q < 4; q++) acc[i][j][q] = 0.0f;

    const int nChunks = (K + 31) / 32;    // 84

    // ---- loader: 3072 x 16B per chunk (Ah 512 | Al 512 | Bh 1024 | Bl 1024) ----
    auto load_chunk = [&](int c) {
        const uint32_t db = sbase + (c & 1) * kBufBytes;
        const int k0 = c * 32;
        #pragma unroll
        for (int t = 0; t < 6; t++) {
            int idx = t * 512 + tid;            // 0..3071
            int kc  = idx & 3;
            int gk  = k0 + kc * 8;
            bool kok = gk < K;
            const __nv_bfloat16* src;
            uint32_t dst;
            bool ok;
            if (idx < 1024) {
                int row = (idx >> 2) & 127;
                const __nv_bfloat16* base = (idx < 512) ? Ahi : Alo;
                dst = db + ((idx < 512) ? 0u : (uint32_t)kATileBytes)
                         + (uint32_t)row * kRowStride + kc * 16;
                src = base + (size_t)(m0 + row) * K + (kok ? gk : 0);
                ok  = kok;
            } else {
                int rem = idx - 1024;           // 0..2047
                int row = (rem >> 2) & 255;
                bool isHi = rem < 1024;
                dst = db + 2u*kATileBytes + (isHi ? 0u : (uint32_t)kBTileBytes)
                         + (uint32_t)row * kRowStride + kc * 16;
                const __nv_bfloat16* base = isHi ? Bhi : Blo;
                int gn = n0 + row;
                bool nok = gn < Nglob;
                src = base + (size_t)(nok ? gn : 0) * K + (kok ? gk : 0);
                ok  = kok && nok;
            }
            cp16(dst, src, ok);
        }
        cp_commit();
    };

    load_chunk(0);

    for (int c = 0; c < nChunks; c++) {
        if (c + 1 < nChunks) { load_chunk(c + 1); cp_wait<1>(); }
        else                 { cp_wait<0>(); }
        __syncthreads();

        const uint32_t db = sbase + (c & 1) * kBufBytes;
        const uint32_t aH = db, aL = db + kATileBytes;
        const uint32_t bH = db + 2*kATileBytes, bL = bH + kBTileBytes;

        #pragma unroll
        for (int ks = 0; ks < 2; ks++) {
            uint32_t ah[4][4], al[4][4], bh[4][2], bl[4][2];
            const int arow = wm + (lane & 15);
            const int acol = ks * 32 + (lane >> 4) * 16;   // bytes
            #pragma unroll
            for (int mt = 0; mt < 4; mt++) {
                uint32_t off = (uint32_t)(arow + mt*16) * kRowStride + acol;
                ldm_x4(ah[mt], aH + off);
                ldm_x4(al[mt], aL + off);
            }
            const int li = lane & 15;
            const int brow = wn + (li & 7);
            const int bcol = ks * 32 + (li >> 3) * 16;     // bytes
            #pragma unroll
            for (int nt = 0; nt < 4; nt++) {
                uint32_t off = (uint32_t)(brow + nt*8) * kRowStride + bcol;
                ldm_x2(bh[nt], bH + off);
                ldm_x2(bl[nt], bL + off);
            }
            #pragma unroll
            for (int mt = 0; mt < 4; mt++)
                #pragma unroll
                for (int nt = 0; nt < 4; nt++) {
                    mma_bf16(acc[mt][nt], ah[mt], bh[nt]);
                    mma_bf16(acc[mt][nt], ah[mt], bl[nt]);
                    mma_bf16(acc[mt][nt], al[mt], bh[nt]);
                }
        }
        __syncthreads();
    }

    // ---- epilogue ----
    #pragma unroll
    for (int mt = 0; mt < 4; mt++) {
        #pragma unroll
        for (int nt = 0; nt < 4; nt++) {
            int row = m0 + wm + mt*16 + (lane >> 2);
            int col = n0 + wn + nt*8 + (lane & 3) * 2;
            #pragma unroll
            for (int half = 0; half < 2; half++) {
                int r = row + half * 8;
                float v0 = acc[mt][nt][half*2 + 0];
                float v1 = acc[mt][nt][half*2 + 1];
                if (col < Nglob) {
                    if (SILU) {
                        v0 = v0 / (1.0f + __expf(-v0));
                        v1 = v1 / (1.0f + __expf(-v1));
                        __nv_bfloat16 h0 = __float2bfloat16(v0);
                        __nv_bfloat16 h1 = __float2bfloat16(v1);
                        size_t o = (size_t)r * Nglob + col;
                        Chi[o]   = h0;
                        Chi[o+1] = h1;
                        Clo[o]   = __float2bfloat16(v0 - __bfloat162float(h0));
                        Clo[o+1] = __float2bfloat16(v1 - __bfloat162float(h1));
                    } else {
                        size_t o = (size_t)r * Nglob + col;
                        Cf[o]   = v0;
                        Cf[o+1] = v1;
                    }
                }
            }
        }
    }
}

// ---------------- stage 5: skinny output GEMMs with fused gating ----------------
template<int OC>
__global__ __launch_bounds__(256)
void skinny_gemm(const float* __restrict__ A, const float* __restrict__ gAll, int gOff,
                 const float* __restrict__ W, float* __restrict__ out,
                 int K, int outBase, int outStride)
{
    constexpr int BR = 32, BK = 32;
    constexpr int G   = 256 / OC;
    constexpr int RPT = BR / G;
    __shared__ float As[BR][BK + 1];
    __shared__ float Ws[BK][OC];
    const int tid  = threadIdx.x;
    const int row0 = blockIdx.x * BR;
    const int col  = tid % OC;
    const int rg   = tid / OC;

    float acc[RPT];
    #pragma unroll
    for (int r = 0; r < RPT; r++) acc[r] = 0.0f;

    for (int k0 = 0; k0 < K; k0 += BK) {
        int r  = tid >> 3;
        int kc = (tid & 7) << 2;
        float4 a4 = make_float4(0.f, 0.f, 0.f, 0.f);
        if (k0 + kc + 4 <= K) {
            a4 = *reinterpret_cast<const float4*>(A + (size_t)(row0 + r)*K + k0 + kc);
            float4 g4 = *reinterpret_cast<const float4*>(
                gAll + (size_t)(row0 + r)*kG + gOff + k0 + kc);
            a4.x *= g4.x; a4.y *= g4.y; a4.z *= g4.z; a4.w *= g4.w;
        }
        As[r][kc] = a4.x; As[r][kc+1] = a4.y; As[r][kc+2] = a4.z; As[r][kc+3] = a4.w;
        for (int idx = tid; idx < BK*OC; idx += 256) {
            int kk = idx / OC, oo = idx % OC;
            Ws[kk][oo] = (k0 + kk < K) ? W[(size_t)(k0 + kk)*OC + oo] : 0.0f;
        }
        __syncthreads();
        #pragma unroll
        for (int kk = 0; kk < BK; kk++) {
            float wv = Ws[kk][col];
            #pragma unroll
            for (int rr = 0; rr < RPT; rr++)
                acc[rr] = fmaf(As[rg + rr*G][kk], wv, acc[rr]);
        }
        __syncthreads();
    }
    #pragma unroll
    for (int rr = 0; rr < RPT; rr++)
        out[(size_t)(row0 + rg + rr*G)*kOUTW + outBase + col*outStride] = acc[rr];
}

// ---------------- launch ----------------
extern "C" void kernel_launch(void* const* d_in, const int* in_sizes, int n_in,
                              void* d_out, int out_size)
{
    const float* xs  = (const float*)d_in[0];
    const float* xv  = (const float*)d_in[1];
    const float* w1  = (const float*)d_in[2];
    const float* w2  = (const float*)d_in[3];
    const float* w0  = (const float*)d_in[4];
    const float* w1o = (const float*)d_in[5];
    const float* w1e = (const float*)d_in[6];
    const float* w2e = (const float*)d_in[7];
    float* out = (float*)d_out;

    void *pf0, *pg, *pf1, *pf1e, *pf2;
    void *pf0hi, *pf0lo, *phhi, *phlo, *pw1h, *pw1l, *pw2h, *pw2l;
    cudaGetSymbolAddress(&pf0,  d_f0);
    cudaGetSymbolAddress(&pg,   d_g);
    cudaGetSymbolAddress(&pf1,  d_f1);
    cudaGetSymbolAddress(&pf1e, d_f1e);
    cudaGetSymbolAddress(&pf2,  d_f2);
    cudaGetSymbolAddress(&pf0hi, d_f0hi);
    cudaGetSymbolAddress(&pf0lo, d_f0lo);
    cudaGetSymbolAddress(&phhi,  d_hhi);
    cudaGetSymbolAddress(&phlo,  d_hlo);
    cudaGetSymbolAddress(&pw1h,  d_w1thi);
    cudaGetSymbolAddress(&pw1l,  d_w1tlo);
    cudaGetSymbolAddress(&pw2h,  d_w2thi);
    cudaGetSymbolAddress(&pw2l,  d_w2tlo);

    float* f0v  = (float*)pf0;
    float* gv   = (float*)pg;
    float* f1v  = (float*)pf1;
    float* f1ev = (float*)pf1e;
    float* f2v  = (float*)pf2;
    __nv_bfloat16* f0hi = (__nv_bfloat16*)pf0hi;
    __nv_bfloat16* f0lo = (__nv_bfloat16*)pf0lo;
    __nv_bfloat16* hhi  = (__nv_bfloat16*)phhi;
    __nv_bfloat16* hlo  = (__nv_bfloat16*)phlo;
    __nv_bfloat16* w1th = (__nv_bfloat16*)pw1h;
    __nv_bfloat16* w1tl = (__nv_bfloat16*)pw1l;
    __nv_bfloat16* w2th = (__nv_bfloat16*)pw2h;
    __nv_bfloat16* w2tl = (__nv_bfloat16*)pw2l;

    cudaFuncSetAttribute(mma_gemm<true>,  cudaFuncAttributeMaxDynamicSharedMemorySize, kGemmSmem);
    cudaFuncSetAttribute(mma_gemm<false>, cudaFuncAttributeMaxDynamicSharedMemorySize, kGemmSmem);

    // stage 0: weight transpose + split
    prep_weight<<<dim3((kM0+31)/32, (kM0+31)/32), 256>>>(w1, w1th, w1tl, kM0, kM0);
    prep_weight<<<dim3((kG +31)/32, (kM0+31)/32), 256>>>(w2, w2th, w2tl, kM0, kG);

    // stage 1: features (+ f0 hi/lo split)
    build_features<<<kN, 256>>>(xs, xv);

    // stage 2: h = silu(f0 @ W1) -> hhi/hlo   [8192 x 2672]
    {
        dim3 grid((kM0 + 255)/256, kN/128);
        mma_gemm<true><<<grid, 512, kGemmSmem>>>(f0hi, f0lo, w1th, w1tl,
                                                 nullptr, hhi, hlo, kM0, kM0);
    }
    // stage 3: g = h @ W2 (fp32)              [8192 x 5776]
    {
        dim3 grid((kG + 255)/256, kN/128);
        mma_gemm<false><<<grid, 512, kGemmSmem>>>(hhi, hlo, w2th, w2tl,
                                                  gv, nullptr, nullptr, kM0, kG);
    }

    // stage 5: gated outputs into [N,288] (gate fused into A-load)
    skinny_gemm<64><<<kN/32, 256>>>(f0v, gv, 0, w0, out, kM0, 0, 1);
    for (int i = 0; i < 3; i++)
        skinny_gemm<32><<<kN/32, 256>>>(f1v + (size_t)i*kN*kM1, gv, kM0,
                                        w1o, out, kM1, 64 + i, 3);
    for (int i = 0; i < 3; i++)
        skinny_gemm<16><<<kN/32, 256>>>(f1ev + (size_t)i*kN*kA1, gv, kM0 + kM1,
                                        w1e, out, kA1, 160 + i, 3);
    for (int m = 0; m < 5; m++)
        skinny_gemm<16><<<kN/32, 256>>>(f2v + (size_t)m*kN*kP1, gv, kM0 + kM1 + kA1,
                                        w2e, out, kP1, 208 + m, 5);
}

// round 5
// speedup vs baseline: 2.8780x; 1.0480x over previous
#include <cuda_runtime.h>
#include <cuda_bf16.h>
#include <cstdint>
#include <math.h>

// ---------------- problem constants ----------------
constexpr int kN    = 8192;
constexpr int kC0   = 64;
constexpr int kC1   = 32;
constexpr int kP0   = kC0*(kC0+1)/2;      // 2080
constexpr int kP1   = kC1*(kC1+1)/2;      // 528
constexpr int kA1   = kC1*(kC1-1)/2;      // 496
constexpr int kM0   = kC0 + kP0 + kP1;    // 2672
constexpr int kM1   = kC1 + kC0*kC1;      // 2080
constexpr int kG    = kM0 + kM1 + kA1 + kP1; // 5776
constexpr int kOUTW = 64 + 32*3 + 16*3 + 16*5; // 288

// ---------------- scratch (static device globals; no allocation) ----------------
__device__ float d_f0 [(size_t)kN*kM0];
__device__ float d_g  [(size_t)kN*kG];
__device__ float d_f1 [3][(size_t)kN*kM1];
__device__ float d_f1e[3][(size_t)kN*kA1];
__device__ float d_f2 [5][(size_t)kN*kP1];
__device__ __nv_bfloat16 d_f0hi[(size_t)kN*kM0];
__device__ __nv_bfloat16 d_f0lo[(size_t)kN*kM0];
__device__ __nv_bfloat16 d_hhi [(size_t)kN*kM0];
__device__ __nv_bfloat16 d_hlo [(size_t)kN*kM0];
__device__ __nv_bfloat16 d_w1thi[(size_t)kM0*kM0];   // [N=2672][K=2672] K-major
__device__ __nv_bfloat16 d_w1tlo[(size_t)kM0*kM0];
__device__ __nv_bfloat16 d_w2thi[(size_t)kG*kM0];    // [N=5776][K=2672] K-major
__device__ __nv_bfloat16 d_w2tlo[(size_t)kG*kM0];

// ---------------- PTX helpers (family-portable: sm_80+ mma.sync / cp.async) ----------------
__device__ __forceinline__ uint32_t smem_u32(const void* p) {
    uint32_t a;
    asm("{ .reg .u64 t; cvta.to.shared.u64 t, %1; cvt.u32.u64 %0, t; }" : "=r"(a) : "l"(p));
    return a;
}
__device__ __forceinline__ void cp16(uint32_t dst, const void* src, bool pred) {
    int sz = pred ? 16 : 0;
    asm volatile("cp.async.cg.shared.global [%0], [%1], 16, %2;"
                 :: "r"(dst), "l"(src), "r"(sz) : "memory");
}
__device__ __forceinline__ void cp_commit() {
    asm volatile("cp.async.commit_group;" ::: "memory");
}
template<int NG>
__device__ __forceinline__ void cp_wait() {
    asm volatile("cp.async.wait_group %0;" :: "n"(NG) : "memory");
}
__device__ __forceinline__ void ldm_x4(uint32_t* r, uint32_t addr) {
    asm volatile("ldmatrix.sync.aligned.m8n8.x4.shared.b16 {%0,%1,%2,%3}, [%4];"
                 : "=r"(r[0]), "=r"(r[1]), "=r"(r[2]), "=r"(r[3]) : "r"(addr));
}
__device__ __forceinline__ void mma_bf16(float* c, const uint32_t* a, const uint32_t* b) {
    asm volatile("mma.sync.aligned.m16n8k16.row.col.f32.bf16.bf16.f32 "
                 "{%0,%1,%2,%3}, {%4,%5,%6,%7}, {%8,%9}, {%0,%1,%2,%3};"
                 : "+f"(c[0]), "+f"(c[1]), "+f"(c[2]), "+f"(c[3])
                 : "r"(a[0]), "r"(a[1]), "r"(a[2]), "r"(a[3]), "r"(b[0]), "r"(b[1]));
}

// ---------------- triu decode ----------------
__device__ __forceinline__ int2 triu_decode(int p, int C, int k)
{
    int Cm = C - k;
    float t = 2.0f*Cm + 1.0f;
    int a = (int)((t - sqrtf(t*t - 8.0f*(float)p)) * 0.5f);
    if (a < 0) a = 0;
    if (a > Cm-1) a = Cm-1;
    while (a > 0 && a*Cm - (a*(a-1))/2 > p) --a;
    while ((a+1)*Cm - ((a+1)*a)/2 <= p) ++a;
    int b = a + k + (p - (a*Cm - (a*(a-1))/2));
    return make_int2(a, b);
}

__device__ __forceinline__ void split_store(float* f, __nv_bfloat16* fh, __nv_bfloat16* fl, int i, float x)
{
    f[i] = x;
    __nv_bfloat16 h = __float2bfloat16(x);
    fh[i] = h;
    fl[i] = __float2bfloat16(x - __bfloat162float(h));
}

// ---------------- stage 0: weight transpose + hi/lo split ----------------
__global__ __launch_bounds__(256)
void prep_weight(const float* __restrict__ W, __nv_bfloat16* __restrict__ Thi,
                 __nv_bfloat16* __restrict__ Tlo, int K, int N)
{
    __shared__ float tile[32][33];
    int kb = blockIdx.y*32, nb = blockIdx.x*32;
    int tx = threadIdx.x & 31, ty = threadIdx.x >> 5;   // 32 x 8
    for (int i = ty; i < 32; i += 8) {
        int k = kb + i, n = nb + tx;
        tile[i][tx] = (k < K && n < N) ? W[(size_t)k*N + n] : 0.f;
    }
    __syncthreads();
    for (int i = ty; i < 32; i += 8) {
        int n = nb + i, k = kb + tx;
        if (n < N && k < K) {
            float x = tile[tx][i];
            __nv_bfloat16 h = __float2bfloat16(x);
            Thi[(size_t)n*K + k] = h;
            Tlo[(size_t)n*K + k] = __float2bfloat16(x - __bfloat162float(h));
        }
    }
}

// ---------------- stage 1: feature construction ----------------
__global__ __launch_bounds__(256)
void build_features(const float* __restrict__ xs, const float* __restrict__ xv)
{
    const int n = blockIdx.x;
    __shared__ float s[kC0];
    __shared__ float v[kC1][3];
    const int t = threadIdx.x;
    if (t < kC0) s[t] = xs[(size_t)n*kC0 + t];
    if (t >= 128 && t < 128 + kC1*3) ((float*)v)[t-128] = xv[(size_t)n*kC1*3 + (t-128)];
    __syncthreads();

    const float RS2 = 0.70710678118654752f;
    const float RS3 = 0.57735026918962576f;
    const float S6  = 0.40824829046386302f;

    float* f0 = d_f0 + (size_t)n*kM0;
    __nv_bfloat16* fh = d_f0hi + (size_t)n*kM0;
    __nv_bfloat16* fl = d_f0lo + (size_t)n*kM0;

    if (t < kC0) split_store(f0, fh, fl, t, s[t]);
    for (int p = t; p < kP0; p += 256) {
        int2 ab = triu_decode(p, kC0, 0);
        float c = (ab.x == ab.y) ? RS2 : 1.0f;
        split_store(f0, fh, fl, kC0 + p, s[ab.x]*s[ab.y]*c);
    }
    for (int p = t; p < kP1; p += 256) {
        int2 ab = triu_decode(p, kC1, 0);
        float c = ((ab.x == ab.y) ? RS2 : 1.0f) * RS3;
        float d = (v[ab.x][0]*v[ab.y][0] + v[ab.x][1]*v[ab.y][1] + v[ab.x][2]*v[ab.y][2]) * c;
        split_store(f0, fh, fl, kC0 + kP0 + p, d);
    }
    for (int c = t; c < kM1; c += 256) {
        float e0, e1, e2;
        if (c < kC1) { e0 = v[c][0]; e1 = v[c][1]; e2 = v[c][2]; }
        else {
            int cc = (c - kC1) >> 5;
            int vv = (c - kC1) & 31;
            float sc = s[cc];
            e0 = sc*v[vv][0]; e1 = sc*v[vv][1]; e2 = sc*v[vv][2];
        }
        size_t idx = (size_t)n*kM1 + c;
        d_f1[0][idx] = e0; d_f1[1][idx] = e1; d_f1[2][idx] = e2;
    }
    for (int p = t; p < kA1; p += 256) {
        int2 ab = triu_decode(p, kC1, 1);
        float ux = v[ab.x][0], uy = v[ab.x][1], uz = v[ab.x][2];
        float wx = v[ab.y][0], wy = v[ab.y][1], wz = v[ab.y][2];
        size_t idx = (size_t)n*kA1 + p;
        d_f1e[0][idx] = (uy*wz - uz*wy) * RS2;
        d_f1e[1][idx] = (uz*wx - ux*wz) * RS2;
        d_f1e[2][idx] = (ux*wy - uy*wx) * RS2;
    }
    for (int p = t; p < kP1; p += 256) {
        int2 ab = triu_decode(p, kC1, 0);
        float c = (ab.x == ab.y) ? RS2 : 1.0f;
        float ax = v[ab.x][0], ay = v[ab.x][1], az = v[ab.x][2];
        float bx = v[ab.y][0], by = v[ab.y][1], bz = v[ab.y][2];
        size_t idx = (size_t)n*kP1 + p;
        d_f2[0][idx] = RS2*(ax*by + ay*bx)*c;
        d_f2[1][idx] = RS2*(ay*bz + az*by)*c;
        d_f2[2][idx] = RS2*(ax*bz + az*bx)*c;
        d_f2[3][idx] = RS2*(ax*bx - ay*by)*c;
        d_f2[4][idx] = S6*(-ax*bx - ay*by + 2.0f*az*bz)*c;
    }
}

// ---- bf16x3 HMMA GEMM: 128x256 tile, 512 thr, BK=32, 3-stage pipeline, 1 barrier/chunk ----
constexpr int kRowStride  = 80;                     // 64B data + 16B pad
constexpr int kATileBytes = 128 * kRowStride;       // 10240
constexpr int kBTileBytes = 256 * kRowStride;       // 20480
constexpr int kBufBytes   = 2*kATileBytes + 2*kBTileBytes; // 61440
constexpr int kStages     = 3;
constexpr int kGemmSmem   = kStages * kBufBytes;    // 184320

template<bool SILU>
__global__ __launch_bounds__(512, 1)
void mma_gemm(const __nv_bfloat16* __restrict__ Ahi, const __nv_bfloat16* __restrict__ Alo,
              const __nv_bfloat16* __restrict__ Bhi, const __nv_bfloat16* __restrict__ Blo,
              float* __restrict__ Cf, __nv_bfloat16* __restrict__ Chi, __nv_bfloat16* __restrict__ Clo,
              int K, int Nglob)
{
    extern __shared__ char smem[];
    const uint32_t sbase = smem_u32(smem);
    const int tid  = threadIdx.x;
    const int wid  = tid >> 5, lane = tid & 31;
    const int m0   = blockIdx.y * 128;
    const int n0   = blockIdx.x * 256;
    const int wm   = (wid & 1) * 64;      // 2 M-warps
    const int wn   = (wid >> 1) * 32;     // 8 N-warps

    float acc[4][4][4];
    #pragma unroll
    for (int i = 0; i < 4; i++)
        #pragma unroll
        for (int j = 0; j < 4; j++)
            #pragma unroll
            for (int q = 0; q < 4; q++) acc[i][j][q] = 0.0f;

    const int nChunks = (K + 31) / 32;    // 84

    // ---- loader: 3072 x 16B per chunk (Ah 512 | Al 512 | Bh 1024 | Bl 1024) ----
    auto load_chunk = [&](int c) {
        const uint32_t db = sbase + (uint32_t)(c % kStages) * kBufBytes;
        const int k0 = c * 32;
        #pragma unroll
        for (int t = 0; t < 6; t++) {
            int idx = t * 512 + tid;            // 0..3071
            int kc  = idx & 3;
            int gk  = k0 + kc * 8;
            bool kok = gk < K;
            const __nv_bfloat16* src;
            uint32_t dst;
            bool ok;
            if (idx < 1024) {
                int row = (idx >> 2) & 127;
                const __nv_bfloat16* base = (idx < 512) ? Ahi : Alo;
                dst = db + ((idx < 512) ? 0u : (uint32_t)kATileBytes)
                         + (uint32_t)row * kRowStride + kc * 16;
                src = base + (size_t)(m0 + row) * K + (kok ? gk : 0);
                ok  = kok;
            } else {
                int rem = idx - 1024;           // 0..2047
                int row = (rem >> 2) & 255;
                bool isHi = rem < 1024;
                dst = db + 2u*kATileBytes + (isHi ? 0u : (uint32_t)kBTileBytes)
                         + (uint32_t)row * kRowStride + kc * 16;
                const __nv_bfloat16* base = isHi ? Bhi : Blo;
                int gn = n0 + row;
                bool nok = gn < Nglob;
                src = base + (size_t)(nok ? gn : 0) * K + (kok ? gk : 0);
                ok  = kok && nok;
            }
            cp16(dst, src, ok);
        }
        cp_commit();
    };

    load_chunk(0);
    load_chunk(1);

    for (int c = 0; c < nChunks; c++) {
        // guarantee chunk c resident (one newer group may stay in flight)
        if (c + 1 < nChunks) cp_wait<1>(); else cp_wait<0>();
        __syncthreads();
        // buffer (c+2)%3 == (c-1)%3: its compute finished before this barrier
        if (c + 2 < nChunks) load_chunk(c + 2);

        const uint32_t db = sbase + (uint32_t)(c % kStages) * kBufBytes;
        const uint32_t aH = db, aL = db + kATileBytes;
        const uint32_t bH = db + 2*kATileBytes, bL = bH + kBTileBytes;

        #pragma unroll
        for (int ks = 0; ks < 2; ks++) {
            uint32_t ah[4][4], al[4][4], bh[4][2], bl[4][2];
            // A frags: x4 per 16-row tile (both k-halves via lane>>4)
            const int arow = wm + (lane & 15);
            const int acol = ks * 32 + (lane >> 4) * 16;   // bytes
            #pragma unroll
            for (int mt = 0; mt < 4; mt++) {
                uint32_t off = (uint32_t)(arow + mt*16) * kRowStride + acol;
                ldm_x4(ah[mt], aH + off);
                ldm_x4(al[mt], aL + off);
            }
            // B frags: one x4 covers two n-tiles (both k-halves), lane-programmed
            const int bg  = lane >> 3;           // matrix index 0..3
            const int br  = lane & 7;
            const int bnt = bg >> 1;             // 0/1: which of the two n-tiles
            const int bkh = (bg & 1) * 16;       // k-half byte offset
            #pragma unroll
            for (int np = 0; np < 2; np++) {     // n-tile pairs (0,1) and (2,3)
                uint32_t off = (uint32_t)(wn + (np*2 + bnt)*8 + br) * kRowStride
                             + ks*32 + bkh;
                ldm_x4(&bh[np*2][0], bH + off);
                ldm_x4(&bl[np*2][0], bL + off);
            }
            #pragma unroll
            for (int mt = 0; mt < 4; mt++)
                #pragma unroll
                for (int nt = 0; nt < 4; nt++) {
                    mma_bf16(acc[mt][nt], ah[mt], bh[nt]);
                    mma_bf16(acc[mt][nt], ah[mt], bl[nt]);
                    mma_bf16(acc[mt][nt], al[mt], bh[nt]);
                }
        }
        // no trailing barrier: next iteration's barrier protects buffer reuse
    }

    // ---- epilogue ----
    #pragma unroll
    for (int mt = 0; mt < 4; mt++) {
        #pragma unroll
        for (int nt = 0; nt < 4; nt++) {
            int row = m0 + wm + mt*16 + (lane >> 2);
            int col = n0 + wn + nt*8 + (lane & 3) * 2;
            #pragma unroll
            for (int half = 0; half < 2; half++) {
                int r = row + half * 8;
                float v0 = acc[mt][nt][half*2 + 0];
                float v1 = acc[mt][nt][half*2 + 1];
                if (col < Nglob) {
                    if (SILU) {
                        v0 = v0 / (1.0f + __expf(-v0));
                        v1 = v1 / (1.0f + __expf(-v1));
                        __nv_bfloat16 h0 = __float2bfloat16(v0);
                        __nv_bfloat16 h1 = __float2bfloat16(v1);
                        size_t o = (size_t)r * Nglob + col;
                        Chi[o]   = h0;
                        Chi[o+1] = h1;
                        Clo[o]   = __float2bfloat16(v0 - __bfloat162float(h0));
                        Clo[o+1] = __float2bfloat16(v1 - __bfloat162float(h1));
                    } else {
                        size_t o = (size_t)r * Nglob + col;
                        Cf[o]   = v0;
                        Cf[o+1] = v1;
                    }
                }
            }
        }
    }
}

// ---------------- stage 5: skinny output GEMMs with fused gating ----------------
template<int OC>
__global__ __launch_bounds__(256)
void skinny_gemm(const float* __restrict__ A, const float* __restrict__ gAll, int gOff,
                 const float* __restrict__ W, float* __restrict__ out,
                 int K, int outBase, int outStride)
{
    constexpr int BR = 32, BK = 32;
    constexpr int G   = 256 / OC;
    constexpr int RPT = BR / G;
    __shared__ float As[BR][BK + 1];
    __shared__ float Ws[BK][OC];
    const int tid  = threadIdx.x;
    const int row0 = blockIdx.x * BR;
    const int col  = tid % OC;
    const int rg   = tid / OC;

    float acc[RPT];
    #pragma unroll
    for (int r = 0; r < RPT; r++) acc[r] = 0.0f;

    for (int k0 = 0; k0 < K; k0 += BK) {
        int r  = tid >> 3;
        int kc = (tid & 7) << 2;
        float4 a4 = make_float4(0.f, 0.f, 0.f, 0.f);
        if (k0 + kc + 4 <= K) {
            a4 = *reinterpret_cast<const float4*>(A + (size_t)(row0 + r)*K + k0 + kc);
            float4 g4 = *reinterpret_cast<const float4*>(
                gAll + (size_t)(row0 + r)*kG + gOff + k0 + kc);
            a4.x *= g4.x; a4.y *= g4.y; a4.z *= g4.z; a4.w *= g4.w;
        }
        As[r][kc] = a4.x; As[r][kc+1] = a4.y; As[r][kc+2] = a4.z; As[r][kc+3] = a4.w;
        for (int idx = tid; idx < BK*OC; idx += 256) {
            int kk = idx / OC, oo = idx % OC;
            Ws[kk][oo] = (k0 + kk < K) ? W[(size_t)(k0 + kk)*OC + oo] : 0.0f;
        }
        __syncthreads();
        #pragma unroll
        for (int kk = 0; kk < BK; kk++) {
            float wv = Ws[kk][col];
            #pragma unroll
            for (int rr = 0; rr < RPT; rr++)
                acc[rr] = fmaf(As[rg + rr*G][kk], wv, acc[rr]);
        }
        __syncthreads();
    }
    #pragma unroll
    for (int rr = 0; rr < RPT; rr++)
        out[(size_t)(row0 + rg + rr*G)*kOUTW + outBase + col*outStride] = acc[rr];
}

// ---------------- launch ----------------
extern "C" void kernel_launch(void* const* d_in, const int* in_sizes, int n_in,
                              void* d_out, int out_size)
{
    const float* xs  = (const float*)d_in[0];
    const float* xv  = (const float*)d_in[1];
    const float* w1  = (const float*)d_in[2];
    const float* w2  = (const float*)d_in[3];
    const float* w0  = (const float*)d_in[4];
    const float* w1o = (const float*)d_in[5];
    const float* w1e = (const float*)d_in[6];
    const float* w2e = (const float*)d_in[7];
    float* out = (float*)d_out;

    void *pf0, *pg, *pf1, *pf1e, *pf2;
    void *pf0hi, *pf0lo, *phhi, *phlo, *pw1h, *pw1l, *pw2h, *pw2l;
    cudaGetSymbolAddress(&pf0,  d_f0);
    cudaGetSymbolAddress(&pg,   d_g);
    cudaGetSymbolAddress(&pf1,  d_f1);
    cudaGetSymbolAddress(&pf1e, d_f1e);
    cudaGetSymbolAddress(&pf2,  d_f2);
    cudaGetSymbolAddress(&pf0hi, d_f0hi);
    cudaGetSymbolAddress(&pf0lo, d_f0lo);
    cudaGetSymbolAddress(&phhi,  d_hhi);
    cudaGetSymbolAddress(&phlo,  d_hlo);
    cudaGetSymbolAddress(&pw1h,  d_w1thi);
    cudaGetSymbolAddress(&pw1l,  d_w1tlo);
    cudaGetSymbolAddress(&pw2h,  d_w2thi);
    cudaGetSymbolAddress(&pw2l,  d_w2tlo);

    float* f0v  = (float*)pf0;
    float* gv   = (float*)pg;
    float* f1v  = (float*)pf1;
    float* f1ev = (float*)pf1e;
    float* f2v  = (float*)pf2;
    __nv_bfloat16* f0hi = (__nv_bfloat16*)pf0hi;
    __nv_bfloat16* f0lo = (__nv_bfloat16*)pf0lo;
    __nv_bfloat16* hhi  = (__nv_bfloat16*)phhi;
    __nv_bfloat16* hlo  = (__nv_bfloat16*)phlo;
    __nv_bfloat16* w1th = (__nv_bfloat16*)pw1h;
    __nv_bfloat16* w1tl = (__nv_bfloat16*)pw1l;
    __nv_bfloat16* w2th = (__nv_bfloat16*)pw2h;
    __nv_bfloat16* w2tl = (__nv_bfloat16*)pw2l;

    cudaFuncSetAttribute(mma_gemm<true>,  cudaFuncAttributeMaxDynamicSharedMemorySize, kGemmSmem);
    cudaFuncSetAttribute(mma_gemm<false>, cudaFuncAttributeMaxDynamicSharedMemorySize, kGemmSmem);

    // stage 0: weight transpose + split
    prep_weight<<<dim3((kM0+31)/32, (kM0+31)/32), 256>>>(w1, w1th, w1tl, kM0, kM0);
    prep_weight<<<dim3((kG +31)/32, (kM0+31)/32), 256>>>(w2, w2th, w2tl, kM0, kG);

    // stage 1: features (+ f0 hi/lo split)
    build_features<<<kN, 256>>>(xs, xv);

    // stage 2: h = silu(f0 @ W1) -> hhi/hlo   [8192 x 2672]
    {
        dim3 grid((kM0 + 255)/256, kN/128);
        mma_gemm<true><<<grid, 512, kGemmSmem>>>(f0hi, f0lo, w1th, w1tl,
                                                 nullptr, hhi, hlo, kM0, kM0);
    }
    // stage 3: g = h @ W2 (fp32)              [8192 x 5776]
    {
        dim3 grid((kG + 255)/256, kN/128);
        mma_gemm<false><<<grid, 512, kGemmSmem>>>(hhi, hlo, w2th, w2tl,
                                                  gv, nullptr, nullptr, kM0, kG);
    }

    // stage 5: gated outputs into [N,288] (gate fused into A-load)
    skinny_gemm<64><<<kN/32, 256>>>(f0v, gv, 0, w0, out, kM0, 0, 1);
    for (int i = 0; i < 3; i++)
        skinny_gemm<32><<<kN/32, 256>>>(f1v + (size_t)i*kN*kM1, gv, kM0,
                                        w1o, out, kM1, 64 + i, 3);
    for (int i = 0; i < 3; i++)
        skinny_gemm<16><<<kN/32, 256>>>(f1ev + (size_t)i*kN*kA1, gv, kM0 + kM1,
                                        w1e, out, kA1, 160 + i, 3);
    for (int m = 0; m < 5; m++)
        skinny_gemm<16><<<kN/32, 256>>>(f2v + (size_t)m*kN*kP1, gv, kM0 + kM1 + kA1,
                                        w2e, out, kP1, 208 + m, 5);
}